// round 2
// baseline (speedup 1.0000x reference)
#include <cuda_runtime.h>
#include <cstdint>

// Problem constants
#define T_C 4
#define N_C 20000
#define E_C 320000
#define FIN 12
#define EH 32
#define NH 64
#define GH 64

// ---------------- device scratch ----------------
__device__ float d_xenc[T_C * N_C * NH];
__device__ float d_xsA [T_C * N_C * NH];
__device__ float d_xsB [T_C * N_C * NH];
__device__ float d_es0 [(size_t)T_C * E_C * EH];
__device__ float d_e1  [(size_t)E_C * EH];
__device__ float d_hx0 [N_C * NH];
__device__ float d_ns  [N_C * NH];
__device__ float d_acc [N_C * NH];
__device__ float d_g[GH], d_gsave[GH];
__device__ float d_gce[EH];
__device__ float d_gcn[NH];
__device__ float d_esum[EH], d_xsum[NH];
__device__ float d_Pp[EH], d_Pm[EH];
__device__ int   d_fast0;

// ---------------- small kernels (unchanged logic) ----------------

__global__ __launch_bounds__(256) void k_encode(const float* __restrict__ na,
                                                const float* __restrict__ W_ne,
                                                const float* __restrict__ b_ne,
                                                float* __restrict__ xenc) {
    __shared__ float sW[FIN * NH + NH];
    for (int i = threadIdx.x; i < FIN * NH + NH; i += 256)
        sW[i] = (i < FIN * NH) ? W_ne[i] : b_ne[i - FIN * NH];
    __syncthreads();
    int idx = blockIdx.x * 256 + threadIdx.x;
    int row = idx >> 6, j = idx & 63;
    float v = sW[FIN * NH + j];
#pragma unroll
    for (int k = 0; k < FIN; k++) v += na[row * FIN + k] * sW[k * NH + j];
    xenc[idx] = fmaxf(v, 0.f);
}

__global__ void k_prep(const float* __restrict__ W_ee, const float* __restrict__ b_ee,
                       const float* __restrict__ W_eb) {
    int j = threadIdx.x;  // 32
    float pp = 0.f, pm = 0.f;
    bool ok = true;
#pragma unroll
    for (int k = 0; k < EH; k++) {
        float w = W_ee[k];
        pp += fmaxf(w, 0.f)  * W_eb[k * EH + j];
        pm += fmaxf(-w, 0.f) * W_eb[k * EH + j];
        if (b_ee[k] != 0.f) ok = false;
    }
    d_Pp[j] = pp; d_Pm[j] = pm;
    if (j == 0) d_fast0 = ok ? 1 : 0;
}

__global__ void k_ginit(const float* __restrict__ g0,
                        const float* __restrict__ W_eb, const float* __restrict__ b_eb,
                        const float* __restrict__ W_nb, const float* __restrict__ b_nb) {
    __shared__ float g[GH];
    int tid = threadIdx.x;  // 96
    if (tid < GH) { g[tid] = g0[tid]; d_g[tid] = g0[tid]; }
    __syncthreads();
    if (tid < EH) {
        float v = b_eb[tid];
#pragma unroll
        for (int k = 0; k < GH; k++) v += g[k] * W_eb[(320 + k) * EH + tid];
        d_gce[tid] = v;
    } else if (tid < 32 + NH) {
        int j = tid - 32;
        float v = b_nb[j];
#pragma unroll
        for (int k = 0; k < GH; k++) v += g[k] * W_nb[(192 + k) * NH + j];
        d_gcn[j] = v;
    }
}

__global__ void k_global(const float* __restrict__ W_gb, const float* __restrict__ b_gb,
                         const float* __restrict__ W_eb, const float* __restrict__ b_eb,
                         const float* __restrict__ W_nb, const float* __restrict__ b_nb,
                         int save) {
    __shared__ float gcat[160], gnew[GH];
    int tid = threadIdx.x;  // 256
    if (tid < 64) gcat[tid] = d_xsum[tid] * (1.0f / N_C);
    else if (tid < 96) gcat[tid] = d_esum[tid - 64] * (1.0f / E_C);
    else if (tid < 160) gcat[tid] = d_g[tid - 96];
    __syncthreads();
    if (tid < GH) {
        float v = b_gb[tid];
        for (int k = 0; k < 160; k++) v += gcat[k] * W_gb[k * GH + tid];
        gnew[tid] = fmaxf(v, 0.f);
    }
    __syncthreads();
    if (tid < GH) {
        d_g[tid] = gnew[tid];
        if (save) d_gsave[tid] = gnew[tid];
        d_xsum[tid] = 0.f;
    }
    if (tid < EH) d_esum[tid] = 0.f;
    if (tid < EH) {
        float v = b_eb[tid];
#pragma unroll
        for (int k = 0; k < GH; k++) v += gnew[k] * W_eb[(320 + k) * EH + tid];
        d_gce[tid] = v;
    } else if (tid < 32 + NH) {
        int j = tid - 32;
        float v = b_nb[j];
#pragma unroll
        for (int k = 0; k < GH; k++) v += gnew[k] * W_nb[(192 + k) * NH + j];
        d_gcn[j] = v;
    }
}

// ---------------- k_nodepre2: ns|nr = [x|h] @ Wpre, 64 nodes/block, also zeroes acc ----------------
// smem: sWt[64][132] (out j -> K row) + sv[64][128]
__global__ __launch_bounds__(256) void k_nodepre2(const float* __restrict__ xin,
                                                  const float* __restrict__ hx,
                                                  const float* __restrict__ W_eb,
                                                  float* __restrict__ ns,
                                                  float* __restrict__ accbuf) {
    extern __shared__ float sm[];
    float* sWt = sm;               // 64*132
    float* sv  = sm + 64 * 132;    // 64*128
    int tid = threadIdx.x;
    // transpose weights: out j: j<32 -> ns (rows 64+k), j>=32 -> nr (rows 192+k)
    for (int idx = tid; idx < 64 * 128; idx += 256) {
        int j = idx & 63, k = idx >> 6;
        int row = ((j < 32) ? 64 : 192) + k;
        sWt[j * 132 + k] = W_eb[row * EH + (j & 31)];
    }
    int base = blockIdx.x * 64;
    for (int idx = tid; idx < 64 * 64; idx += 256) {
        int n = idx >> 6, c = idx & 63;
        int gn = base + n;
        float vx = 0.f, vh = 0.f;
        if (gn < N_C) { vx = xin[(size_t)gn * 64 + c]; vh = hx[(size_t)gn * 64 + c]; }
        sv[n * 128 + c] = vx;
        sv[n * 128 + 64 + c] = vh;
    }
    __syncthreads();
    int lane = tid & 31, wid = tid >> 5;
    float accA[8], accB[8];
#pragma unroll
    for (int i = 0; i < 8; i++) { accA[i] = 0.f; accB[i] = 0.f; }
    const float4* wa4 = (const float4*)&sWt[lane * 132];
    const float4* wb4 = (const float4*)&sWt[(lane + 32) * 132];
#pragma unroll
    for (int q = 0; q < 32; q++) {
        float4 wa = wa4[q], wb = wb4[q];
#pragma unroll
        for (int nn = 0; nn < 8; nn++) {
            float4 v = *(const float4*)&sv[(wid * 8 + nn) * 128 + q * 4];
            accA[nn] += v.x * wa.x + v.y * wa.y + v.z * wa.z + v.w * wa.w;
            accB[nn] += v.x * wb.x + v.y * wb.y + v.z * wb.z + v.w * wb.w;
        }
    }
#pragma unroll
    for (int nn = 0; nn < 8; nn++) {
        int gn = base + wid * 8 + nn;
        if (gn < N_C) {
            ns[(size_t)gn * 64 + lane] = accA[nn];
            ns[(size_t)gn * 64 + 32 + lane] = accB[nn];
            accbuf[(size_t)gn * 64 + lane] = 0.f;
            accbuf[(size_t)gn * 64 + 32 + lane] = 0.f;
        }
    }
}

// ---------------- k_edge2: register-weight GEMV, 64 edges/block ----------------
template <bool L0, bool HE>
__global__ __launch_bounds__(256) void k_edge2(const int* __restrict__ eidx,
                                               const float* __restrict__ ea_t,
                                               const float* __restrict__ ein,
                                               const float* __restrict__ he,
                                               float* __restrict__ eout,
                                               const float* __restrict__ ns,
                                               float* __restrict__ accbuf,
                                               const float* __restrict__ W_eb,
                                               const float* __restrict__ W_ee,
                                               const float* __restrict__ b_ee) {
    __shared__ __align__(16) float svA[64 * 32];
    __shared__ __align__(16) float svB[HE ? 64 * 32 : 32];
    __shared__ float sa[64];
    __shared__ float sred[8 * 32];
    int tid = threadIdx.x;
    int lane = tid & 31, wid = tid >> 5;
    int e0 = blockIdx.x * 64;
    int fast = L0 ? d_fast0 : 0;

    if (L0) {
        if (tid < 64) sa[tid] = ea_t[e0 + tid];
        if (!fast) {
            // general fallback: stage relu(a*W_ee + b_ee)
            for (int idx = tid; idx < 64 * 32; idx += 256) {
                int e = idx >> 5, k = idx & 31;
                svA[idx] = fmaxf(ea_t[e0 + e] * W_ee[k] + b_ee[k], 0.f);
            }
        }
    } else {
        for (int idx = tid; idx < 64 * 32; idx += 256)
            svA[idx] = ein[(size_t)e0 * 32 + idx];
    }
    if (HE) {
        for (int idx = tid; idx < 64 * 32; idx += 256)
            svB[idx] = he[(size_t)e0 * 32 + idx];
    }

    // weights into registers
    float w_in[32], w_he[32];
    if (!L0 || !fast) {
#pragma unroll
        for (int k = 0; k < 32; k++) w_in[k] = W_eb[k * EH + lane];
    }
    if (HE) {
#pragma unroll
        for (int k = 0; k < 32; k++) w_he[k] = W_eb[(32 + k) * EH + lane];
    }
    float gce = d_gce[lane];
    float pp = 0.f, pm = 0.f;
    if (L0) { pp = d_Pp[lane]; pm = d_Pm[lane]; }
    __syncthreads();

    float esum = 0.f;
#pragma unroll 2
    for (int i = 0; i < 8; i++) {
        int e = e0 + wid * 8 + i;
        int s = __ldg(&eidx[e]);
        int r = __ldg(&eidx[E_C + e]);
        float g1 = ns[(size_t)s * 64 + lane];
        float g2 = ns[(size_t)r * 64 + 32 + lane];
        float acc = gce;
        if (L0 && fast) {
            float a = sa[wid * 8 + i];
            acc += (a >= 0.f) ? a * pp : -a * pm;
        } else {
            const float4* vp = (const float4*)&svA[(wid * 8 + i) * 32];
#pragma unroll
            for (int q = 0; q < 8; q++) {
                float4 v = vp[q];
                acc += v.x * w_in[q * 4] + v.y * w_in[q * 4 + 1] +
                       v.z * w_in[q * 4 + 2] + v.w * w_in[q * 4 + 3];
            }
        }
        if (HE) {
            const float4* vp = (const float4*)&svB[(wid * 8 + i) * 32];
#pragma unroll
            for (int q = 0; q < 8; q++) {
                float4 v = vp[q];
                acc += v.x * w_he[q * 4] + v.y * w_he[q * 4 + 1] +
                       v.z * w_he[q * 4 + 2] + v.w * w_he[q * 4 + 3];
            }
        }
        acc += g1 + g2;
        float en = fmaxf(acc, 0.f);
        eout[(size_t)e * 32 + lane] = en;
        atomicAdd(&accbuf[(size_t)s * 64 + lane], en);
        atomicAdd(&accbuf[(size_t)r * 64 + 32 + lane], en);
        esum += en;
    }
    sred[wid * 32 + lane] = esum;
    __syncthreads();
    if (wid == 0) {
        float s2 = 0.f;
#pragma unroll
        for (int w = 0; w < 8; w++) s2 += sred[w * 32 + lane];
        atomicAdd(&d_esum[lane], s2);
    }
}

// ---------------- k_node2: x_new = relu([x|h|acc]@W_nb + gcn), 64 nodes/block ----------------
// smem: sWt[64][196] + sv[64][192]; sv reused for xsum reduction
__global__ __launch_bounds__(256) void k_node2(const float* __restrict__ xin,
                                               const float* __restrict__ hx,
                                               const float* __restrict__ accbuf,
                                               const float* __restrict__ W_nb,
                                               float* __restrict__ xsout,
                                               float* __restrict__ tdout) {
    extern __shared__ float sm[];
    float* sWt = sm;                // 64*196
    float* sv  = sm + 64 * 196;     // 64*192
    int tid = threadIdx.x;
    for (int idx = tid; idx < 192 * 64; idx += 256)
        sWt[(idx & 63) * 196 + (idx >> 6)] = W_nb[idx];
    int base = blockIdx.x * 64;
    for (int idx = tid; idx < 64 * 64; idx += 256) {
        int n = idx >> 6, c = idx & 63;
        int gn = base + n;
        float vx = 0.f, vh = 0.f, va = 0.f;
        if (gn < N_C) {
            vx = xin[(size_t)gn * 64 + c];
            vh = hx[(size_t)gn * 64 + c];
            va = accbuf[(size_t)gn * 64 + c];
        }
        sv[n * 192 + c] = vx;
        sv[n * 192 + 64 + c] = vh;
        sv[n * 192 + 128 + c] = va;
    }
    __syncthreads();
    int lane = tid & 31, wid = tid >> 5;
    float accA[8], accB[8];
#pragma unroll
    for (int i = 0; i < 8; i++) { accA[i] = 0.f; accB[i] = 0.f; }
    const float4* wa4 = (const float4*)&sWt[lane * 196];
    const float4* wb4 = (const float4*)&sWt[(lane + 32) * 196];
#pragma unroll
    for (int q = 0; q < 48; q++) {
        float4 wa = wa4[q], wb = wb4[q];
#pragma unroll
        for (int nn = 0; nn < 8; nn++) {
            float4 v = *(const float4*)&sv[(wid * 8 + nn) * 192 + q * 4];
            accA[nn] += v.x * wa.x + v.y * wa.y + v.z * wa.z + v.w * wa.w;
            accB[nn] += v.x * wb.x + v.y * wb.y + v.z * wb.z + v.w * wb.w;
        }
    }
    float gA = d_gcn[lane], gB = d_gcn[32 + lane];
    float sA = 0.f, sB = 0.f;
    float h0, h1;
#pragma unroll
    for (int nn = 0; nn < 8; nn++) {
        int gn = base + wid * 8 + nn;
        if (gn < N_C) {
            float lo = fmaxf(accA[nn] + gA, 0.f);
            float hi = fmaxf(accB[nn] + gB, 0.f);
            xsout[(size_t)gn * 64 + lane] = lo;
            xsout[(size_t)gn * 64 + 32 + lane] = hi;
            if (tdout) {
                h0 = sv[(wid * 8 + nn) * 192 + 64 + lane];
                h1 = sv[(wid * 8 + nn) * 192 + 96 + lane];
                tdout[(size_t)gn * 64 + lane] = lo - h0;
                tdout[(size_t)gn * 64 + 32 + lane] = hi - h1;
            }
            sA += lo; sB += hi;
        }
    }
    __syncthreads();
    // reuse sv for reduction
    sv[wid * 64 + lane] = sA;
    sv[wid * 64 + 32 + lane] = sB;
    __syncthreads();
    if (tid < 64) {
        float s2 = 0.f;
#pragma unroll
        for (int w = 0; w < 8; w++) s2 += sv[w * 64 + tid];
        atomicAdd(&d_xsum[tid], s2);
    }
}

// ---------------- sder / resid / decode (round-1 versions) ----------------
__global__ __launch_bounds__(256) void k_sder(const int* __restrict__ eidx,
                                              const float* __restrict__ spL,
                                              const float* __restrict__ coeff,
                                              const float* __restrict__ xs,
                                              float* __restrict__ sd) {
    int tid = threadIdx.x, lane = tid & 31, wid = tid >> 5;
    int e = blockIdx.x * 8 + wid;
    int s = eidx[e], r = eidx[E_C + e];
    float cw = coeff[0] * spL[e];
    size_t bs = (size_t)s * NH, br = (size_t)r * NH;
    float d0 = cw * (xs[bs + lane] - xs[br + lane]);
    float d1 = cw * (xs[bs + 32 + lane] - xs[br + 32 + lane]);
    atomicAdd(&sd[br + lane], d0);
    atomicAdd(&sd[br + 32 + lane], d1);
}

__global__ __launch_bounds__(256) void k_resid(float* __restrict__ a, const float* __restrict__ b) {
    int i = blockIdx.x * 256 + threadIdx.x;
    a[i] += b[i];
}

__global__ __launch_bounds__(256) void k_decode(const float* __restrict__ xa,
                                                const float* __restrict__ xb,
                                                const float* __restrict__ W1,
                                                const float* __restrict__ b1,
                                                const float* __restrict__ W2,
                                                const float* __restrict__ b2,
                                                float* __restrict__ outn) {
    __shared__ float sW[NH * NH];
    __shared__ float sw2[NH];
    int tid = threadIdx.x;
    for (int i = tid; i < NH * NH; i += 256) sW[i] = W1[i];
    if (tid < NH) sw2[tid] = W2[tid];
    __syncthreads();
    int lane = tid & 31, wid = tid >> 5;
    int row = blockIdx.x * 8 + wid;
    size_t b = (size_t)row * NH;
    float x0 = xa[b + lane] + xb[b + lane];
    float x1 = xa[b + 32 + lane] + xb[b + 32 + lane];
    float lo = b1[lane], hi = b1[32 + lane];
#pragma unroll
    for (int k = 0; k < 32; k++) {
        float v = __shfl_sync(0xffffffffu, x0, k);
        lo += v * sW[k * NH + lane]; hi += v * sW[k * NH + 32 + lane];
    }
#pragma unroll
    for (int k = 0; k < 32; k++) {
        float v = __shfl_sync(0xffffffffu, x1, k);
        lo += v * sW[(32 + k) * NH + lane]; hi += v * sW[(32 + k) * NH + 32 + lane];
    }
    lo = fmaxf(lo, 0.f); hi = fmaxf(hi, 0.f);
    float p = lo * sw2[lane] + hi * sw2[32 + lane];
#pragma unroll
    for (int o = 16; o; o >>= 1) p += __shfl_down_sync(0xffffffffu, p, o);
    if (lane == 0) outn[row] = p + b2[0];
}

// ---------------- host launcher ----------------
extern "C" void kernel_launch(void* const* d_in, const int* in_sizes, int n_in,
                              void* d_out, int out_size) {
    const float* node_attr  = (const float*)d_in[0];
    const float* edge_attr  = (const float*)d_in[1];
    const int*   edge_index = (const int*)  d_in[2];
    const float* spL        = (const float*)d_in[3];
    const float* gattr      = (const float*)d_in[4];
    const float* coeff      = (const float*)d_in[5];
    const float* W_ee = (const float*)d_in[6];
    const float* b_ee = (const float*)d_in[7];
    const float* W_ne = (const float*)d_in[8];
    const float* b_ne = (const float*)d_in[9];
    const float* W_eb = (const float*)d_in[10];
    const float* b_eb = (const float*)d_in[11];
    const float* W_nb = (const float*)d_in[12];
    const float* b_nb = (const float*)d_in[13];
    const float* W_gb = (const float*)d_in[14];
    const float* b_gb = (const float*)d_in[15];
    const float* W_nd1 = (const float*)d_in[16];
    const float* b_nd1 = (const float*)d_in[17];
    const float* W_nd2 = (const float*)d_in[18];
    const float* b_nd2 = (const float*)d_in[19];

    float* out    = (float*)d_out;
    float* out_td = out + (size_t)T_C * N_C;
    float* out_sd = out_td + (size_t)T_C * N_C * NH;

    float *xenc, *xsA, *xsB, *es0, *e1, *hx0, *ns, *acc, *gsave, *esum, *xsum;
    cudaGetSymbolAddress((void**)&xenc, d_xenc);
    cudaGetSymbolAddress((void**)&xsA,  d_xsA);
    cudaGetSymbolAddress((void**)&xsB,  d_xsB);
    cudaGetSymbolAddress((void**)&es0,  d_es0);
    cudaGetSymbolAddress((void**)&e1,   d_e1);
    cudaGetSymbolAddress((void**)&hx0,  d_hx0);
    cudaGetSymbolAddress((void**)&ns,   d_ns);
    cudaGetSymbolAddress((void**)&acc,  d_acc);
    cudaGetSymbolAddress((void**)&gsave, d_gsave);
    cudaGetSymbolAddress((void**)&esum, d_esum);
    cudaGetSymbolAddress((void**)&xsum, d_xsum);

    const int PRE_SMEM  = (64 * 132 + 64 * 128) * (int)sizeof(float);  // 66560
    const int NODE_SMEM = (64 * 196 + 64 * 192) * (int)sizeof(float);  // 99328
    cudaFuncSetAttribute(k_nodepre2, cudaFuncAttributeMaxDynamicSharedMemorySize, PRE_SMEM);
    cudaFuncSetAttribute(k_node2,    cudaFuncAttributeMaxDynamicSharedMemorySize, NODE_SMEM);

    const int NGRID = (N_C + 63) / 64;   // 313
    const int EGRID = E_C / 64;          // 5000

    cudaMemsetAsync(hx0, 0, (size_t)N_C * NH * sizeof(float));
    cudaMemsetAsync(esum, 0, EH * sizeof(float));
    cudaMemsetAsync(xsum, 0, NH * sizeof(float));
    cudaMemsetAsync(out_sd, 0, (size_t)T_C * N_C * NH * sizeof(float));

    k_encode<<<(T_C * N_C * NH) / 256, 256>>>(node_attr, W_ne, b_ne, xenc);
    k_prep<<<1, 32>>>(W_ee, b_ee, W_eb);

    // ---------------- layer 0 ----------------
    k_ginit<<<1, 96>>>(gattr, W_eb, b_eb, W_nb, b_nb);
    for (int t = 0; t < T_C; t++) {
        const float* xin = xenc + (size_t)t * N_C * NH;
        const float* hx = t ? (xsA + (size_t)(t - 1) * N_C * NH) : hx0;
        k_nodepre2<<<NGRID, 256, PRE_SMEM>>>(xin, hx, W_eb, ns, acc);
        if (t == 0)
            k_edge2<true, false><<<EGRID, 256>>>(edge_index, edge_attr + (size_t)t * E_C,
                                                 nullptr, nullptr,
                                                 es0 + (size_t)t * E_C * EH, ns, acc,
                                                 W_eb, W_ee, b_ee);
        else
            k_edge2<true, true><<<EGRID, 256>>>(edge_index, edge_attr + (size_t)t * E_C,
                                                nullptr, es0 + (size_t)(t - 1) * E_C * EH,
                                                es0 + (size_t)t * E_C * EH, ns, acc,
                                                W_eb, W_ee, b_ee);
        k_node2<<<NGRID, 256, NODE_SMEM>>>(xin, hx, acc, W_nb,
                                           xsA + (size_t)t * N_C * NH, nullptr);
        if (t < T_C - 1)
            k_global<<<1, 256>>>(W_gb, b_gb, W_eb, b_eb, W_nb, b_nb, t == 0 ? 1 : 0);
    }

    k_resid<<<(T_C * N_C * NH) / 256, 256>>>(xsA, xenc);
    cudaMemsetAsync(esum, 0, EH * sizeof(float));
    cudaMemsetAsync(xsum, 0, NH * sizeof(float));

    // ---------------- layer 1 ----------------
    k_ginit<<<1, 96>>>(gsave, W_eb, b_eb, W_nb, b_nb);
    for (int t = 0; t < T_C; t++) {
        const float* xin = xsA + (size_t)t * N_C * NH;
        const float* hx = t ? (xsB + (size_t)(t - 1) * N_C * NH) : hx0;
        k_nodepre2<<<NGRID, 256, PRE_SMEM>>>(xin, hx, W_eb, ns, acc);
        if (t == 0)
            k_edge2<false, false><<<EGRID, 256>>>(edge_index, nullptr,
                                                  es0 + (size_t)t * E_C * EH, nullptr,
                                                  e1, ns, acc, W_eb, W_ee, b_ee);
        else
            k_edge2<false, true><<<EGRID, 256>>>(edge_index, nullptr,
                                                 es0 + (size_t)t * E_C * EH, e1,
                                                 e1, ns, acc, W_eb, W_ee, b_ee);
        k_node2<<<NGRID, 256, NODE_SMEM>>>(xin, hx, acc, W_nb,
                                           xsB + (size_t)t * N_C * NH,
                                           out_td + (size_t)t * N_C * NH);
        if (t < T_C - 1)
            k_global<<<1, 256>>>(W_gb, b_gb, W_eb, b_eb, W_nb, b_nb, 0);
        k_sder<<<E_C / 8, 256>>>(edge_index, spL, coeff,
                                 xsB + (size_t)t * N_C * NH,
                                 out_sd + (size_t)t * N_C * NH);
    }

    k_decode<<<(T_C * N_C) / 8, 256>>>(xsA, xsB, W_nd1, b_nd1, W_nd2, b_nd2, out);
}

// round 3
// speedup vs baseline: 1.1507x; 1.1507x over previous
#include <cuda_runtime.h>
#include <cstdint>

// Problem constants
#define T_C 4
#define N_C 20000
#define E_C 320000
#define FIN 12
#define EH 32
#define NH 64
#define GH 64

// ---------------- device scratch ----------------
__device__ float d_xenc[T_C * N_C * NH];
__device__ float d_xsA [T_C * N_C * NH];
__device__ float d_xsB [T_C * N_C * NH];
__device__ float d_es0 [(size_t)T_C * E_C * EH];
__device__ float d_e1  [(size_t)E_C * EH];
__device__ float d_hx0 [N_C * NH];
__device__ float d_ns  [N_C * NH];
__device__ float d_acc [N_C * NH];
__device__ float d_g[GH], d_gsave[GH];
__device__ float d_gce[EH];
__device__ float d_gcn[NH];
__device__ float d_esum[EH], d_xsum[NH];
__device__ float d_Pp[EH], d_Pm[EH];
__device__ int   d_fast0;

__device__ __forceinline__ float dot4(float4 v, float4 w) {
    return v.x * w.x + v.y * w.y + v.z * w.z + v.w * w.w;
}

// ---------------- small kernels ----------------

__global__ __launch_bounds__(256) void k_encode(const float* __restrict__ na,
                                                const float* __restrict__ W_ne,
                                                const float* __restrict__ b_ne,
                                                float* __restrict__ xenc) {
    __shared__ float sW[FIN * NH + NH];
    for (int i = threadIdx.x; i < FIN * NH + NH; i += 256)
        sW[i] = (i < FIN * NH) ? W_ne[i] : b_ne[i - FIN * NH];
    __syncthreads();
    int idx = blockIdx.x * 256 + threadIdx.x;
    int row = idx >> 6, j = idx & 63;
    float v = sW[FIN * NH + j];
#pragma unroll
    for (int k = 0; k < FIN; k++) v += na[row * FIN + k] * sW[k * NH + j];
    xenc[idx] = fmaxf(v, 0.f);
}

__global__ void k_prep(const float* __restrict__ W_ee, const float* __restrict__ b_ee,
                       const float* __restrict__ W_eb) {
    int j = threadIdx.x;  // 32
    float pp = 0.f, pm = 0.f;
    bool ok = true;
#pragma unroll
    for (int k = 0; k < EH; k++) {
        float w = W_ee[k];
        pp += fmaxf(w, 0.f)  * W_eb[k * EH + j];
        pm += fmaxf(-w, 0.f) * W_eb[k * EH + j];
        if (b_ee[k] != 0.f) ok = false;
    }
    d_Pp[j] = pp; d_Pm[j] = pm;
    if (j == 0) d_fast0 = ok ? 1 : 0;
}

__global__ void k_ginit(const float* __restrict__ g0,
                        const float* __restrict__ W_eb, const float* __restrict__ b_eb,
                        const float* __restrict__ W_nb, const float* __restrict__ b_nb) {
    __shared__ float g[GH];
    int tid = threadIdx.x;  // 96
    if (tid < GH) { g[tid] = g0[tid]; d_g[tid] = g0[tid]; }
    __syncthreads();
    if (tid < EH) {
        float v = b_eb[tid];
#pragma unroll
        for (int k = 0; k < GH; k++) v += g[k] * W_eb[(320 + k) * EH + tid];
        d_gce[tid] = v;
    } else if (tid < 32 + NH) {
        int j = tid - 32;
        float v = b_nb[j];
#pragma unroll
        for (int k = 0; k < GH; k++) v += g[k] * W_nb[(192 + k) * NH + j];
        d_gcn[j] = v;
    }
}

__global__ void k_global(const float* __restrict__ W_gb, const float* __restrict__ b_gb,
                         const float* __restrict__ W_eb, const float* __restrict__ b_eb,
                         const float* __restrict__ W_nb, const float* __restrict__ b_nb,
                         int save) {
    __shared__ float gcat[160], gnew[GH];
    int tid = threadIdx.x;  // 256
    if (tid < 64) gcat[tid] = d_xsum[tid] * (1.0f / N_C);
    else if (tid < 96) gcat[tid] = d_esum[tid - 64] * (1.0f / E_C);
    else if (tid < 160) gcat[tid] = d_g[tid - 96];
    __syncthreads();
    if (tid < GH) {
        float v = b_gb[tid];
        for (int k = 0; k < 160; k++) v += gcat[k] * W_gb[k * GH + tid];
        gnew[tid] = fmaxf(v, 0.f);
    }
    __syncthreads();
    if (tid < GH) {
        d_g[tid] = gnew[tid];
        if (save) d_gsave[tid] = gnew[tid];
        d_xsum[tid] = 0.f;
    }
    if (tid < EH) d_esum[tid] = 0.f;
    if (tid < EH) {
        float v = b_eb[tid];
#pragma unroll
        for (int k = 0; k < GH; k++) v += gnew[k] * W_eb[(320 + k) * EH + tid];
        d_gce[tid] = v;
    } else if (tid < 32 + NH) {
        int j = tid - 32;
        float v = b_nb[j];
#pragma unroll
        for (int k = 0; k < GH; k++) v += gnew[k] * W_nb[(192 + k) * NH + j];
        d_gcn[j] = v;
    }
}

// ---------------- k_nodepre3: ns|nr = [x|h] @ Wpre, weights-only smem, broadcast LDG values ----------------
__global__ __launch_bounds__(256) void k_nodepre3(const float* __restrict__ xin,
                                                  const float* __restrict__ hx,
                                                  const float* __restrict__ W_eb,
                                                  float* __restrict__ ns,
                                                  float* __restrict__ accbuf) {
    __shared__ float4 sW[64 * 33];   // out j (0..63) x 32 quads, pad 33 -> conflict-free
    int tid = threadIdx.x;
    for (int idx = tid; idx < 64 * 32; idx += 256) {
        int j = idx >> 5, q = idx & 31;
        // q<16: x-part rows (j<32 ? 64 : 192)+4q ; q>=16: h-part rows (j<32 ? 128 : 256)+4(q-16)
        int row0 = ((q < 16) ? ((j < 32) ? 64 : 192) + 4 * q
                             : ((j < 32) ? 128 : 256) + 4 * (q - 16));
        int jj = j & 31;
        float4 w;
        w.x = W_eb[(row0 + 0) * EH + jj];
        w.y = W_eb[(row0 + 1) * EH + jj];
        w.z = W_eb[(row0 + 2) * EH + jj];
        w.w = W_eb[(row0 + 3) * EH + jj];
        sW[j * 33 + q] = w;
    }
    __syncthreads();
    int lane = tid & 31, wid = tid >> 5;
    int gn0 = blockIdx.x * 64 + wid * 8;
    size_t off[8];
#pragma unroll
    for (int n = 0; n < 8; n++) {
        int gn = gn0 + n;
        off[n] = (size_t)((gn < N_C) ? gn : 0) * 64;
    }
    float aA[8], aB[8];
#pragma unroll
    for (int n = 0; n < 8; n++) { aA[n] = 0.f; aB[n] = 0.f; }
#pragma unroll
    for (int q = 0; q < 16; q++) {
        float4 wa = sW[lane * 33 + q], wb = sW[(lane + 32) * 33 + q];
#pragma unroll
        for (int n = 0; n < 8; n++) {
            float4 v = *(const float4*)&xin[off[n] + 4 * q];
            aA[n] += dot4(v, wa); aB[n] += dot4(v, wb);
        }
    }
#pragma unroll
    for (int q = 0; q < 16; q++) {
        float4 wa = sW[lane * 33 + 16 + q], wb = sW[(lane + 32) * 33 + 16 + q];
#pragma unroll
        for (int n = 0; n < 8; n++) {
            float4 v = *(const float4*)&hx[off[n] + 4 * q];
            aA[n] += dot4(v, wa); aB[n] += dot4(v, wb);
        }
    }
#pragma unroll
    for (int n = 0; n < 8; n++) {
        int gn = gn0 + n;
        if (gn < N_C) {
            ns[(size_t)gn * 64 + lane] = aA[n];
            ns[(size_t)gn * 64 + 32 + lane] = aB[n];
            accbuf[(size_t)gn * 64 + lane] = 0.f;
            accbuf[(size_t)gn * 64 + 32 + lane] = 0.f;
        }
    }
}

// ---------------- k_edge3: 128 edges/block, 16 edges/warp, weights in smem ----------------
template <bool L0, bool HE>
__global__ __launch_bounds__(256) void k_edge3(const int* __restrict__ eidx,
                                               const float* __restrict__ ea_t,
                                               const float* __restrict__ ein,
                                               const float* __restrict__ he,
                                               float* __restrict__ eout,
                                               const float* __restrict__ ns,
                                               float* __restrict__ accbuf,
                                               const float* __restrict__ W_eb,
                                               const float* __restrict__ W_ee,
                                               const float* __restrict__ b_ee) {
    __shared__ float4 sWA[32 * 9];   // rows 0..31 (e_in), out=lane, pad 9 quads
    __shared__ float4 sWB[HE ? 32 * 9 : 1];
    __shared__ float4 sWee[8], sBee[8];
    __shared__ float sa[L0 ? 128 : 1];
    __shared__ float sred[8 * 32];
    int tid = threadIdx.x;
    int lane = tid & 31, wid = tid >> 5;
    int fast = L0 ? d_fast0 : 0;

    for (int idx = tid; idx < 32 * 8; idx += 256) {
        int j = idx >> 3, q = idx & 7;
        float4 w;
        w.x = W_eb[(4 * q + 0) * EH + j];
        w.y = W_eb[(4 * q + 1) * EH + j];
        w.z = W_eb[(4 * q + 2) * EH + j];
        w.w = W_eb[(4 * q + 3) * EH + j];
        sWA[j * 9 + q] = w;
        if (HE) {
            float4 w2;
            w2.x = W_eb[(32 + 4 * q + 0) * EH + j];
            w2.y = W_eb[(32 + 4 * q + 1) * EH + j];
            w2.z = W_eb[(32 + 4 * q + 2) * EH + j];
            w2.w = W_eb[(32 + 4 * q + 3) * EH + j];
            sWB[j * 9 + q] = w2;
        }
    }
    int e0b = blockIdx.x * 128;
    if (L0) {
        if (tid < 128) sa[tid] = ea_t[e0b + tid];
        if (tid < 8) {
            sWee[tid] = *(const float4*)&W_ee[tid * 4];
            sBee[tid] = *(const float4*)&b_ee[tid * 4];
        }
    }
    float gce = d_gce[lane];
    float pp = 0.f, pm = 0.f;
    if (L0) { pp = d_Pp[lane]; pm = d_Pm[lane]; }
    __syncthreads();

    int e0 = e0b + wid * 16;
    float acc[16];
#pragma unroll
    for (int i = 0; i < 16; i++) acc[i] = gce;

    if (L0) {
        if (fast) {
#pragma unroll
            for (int i = 0; i < 16; i++) {
                float a = sa[wid * 16 + i];
                acc[i] += (a >= 0.f) ? a * pp : -a * pm;
            }
        } else {
#pragma unroll
            for (int q = 0; q < 8; q++) {
                float4 w = sWA[lane * 9 + q];
                float4 we = sWee[q], be = sBee[q];
#pragma unroll
                for (int i = 0; i < 16; i++) {
                    float a = sa[wid * 16 + i];
                    float4 v;
                    v.x = fmaxf(a * we.x + be.x, 0.f);
                    v.y = fmaxf(a * we.y + be.y, 0.f);
                    v.z = fmaxf(a * we.z + be.z, 0.f);
                    v.w = fmaxf(a * we.w + be.w, 0.f);
                    acc[i] += dot4(v, w);
                }
            }
        }
    } else {
#pragma unroll
        for (int q = 0; q < 8; q++) {
            float4 w = sWA[lane * 9 + q];
#pragma unroll
            for (int i = 0; i < 16; i++) {
                float4 v = *(const float4*)&ein[(size_t)(e0 + i) * 32 + 4 * q];
                acc[i] += dot4(v, w);
            }
        }
    }
    if (HE) {
#pragma unroll
        for (int q = 0; q < 8; q++) {
            float4 w = sWB[lane * 9 + q];
#pragma unroll
            for (int i = 0; i < 16; i++) {
                float4 v = *(const float4*)&he[(size_t)(e0 + i) * 32 + 4 * q];
                acc[i] += dot4(v, w);
            }
        }
    }

    float esum = 0.f;
#pragma unroll 4
    for (int i = 0; i < 16; i++) {
        int e = e0 + i;
        int s = __ldg(&eidx[e]);
        int r = __ldg(&eidx[E_C + e]);
        float t1 = ns[(size_t)s * 64 + lane];
        float t2 = ns[(size_t)r * 64 + 32 + lane];
        float en = fmaxf(acc[i] + t1 + t2, 0.f);
        eout[(size_t)e * 32 + lane] = en;
        atomicAdd(&accbuf[(size_t)s * 64 + lane], en);
        atomicAdd(&accbuf[(size_t)r * 64 + 32 + lane], en);
        esum += en;
    }
    sred[wid * 32 + lane] = esum;
    __syncthreads();
    if (wid == 0) {
        float s2 = 0.f;
#pragma unroll
        for (int w = 0; w < 8; w++) s2 += sred[w * 32 + lane];
        atomicAdd(&d_esum[lane], s2);
    }
}

// ---------------- k_node3: x_new = relu([x|h|acc]@W_nb + gcn), weights-only smem ----------------
__global__ __launch_bounds__(256) void k_node3(const float* __restrict__ xin,
                                               const float* __restrict__ hx,
                                               const float* __restrict__ accbuf,
                                               const float* __restrict__ W_nb,
                                               float* __restrict__ xsout,
                                               float* __restrict__ tdout) {
    __shared__ float4 sW[64 * 49];   // out j (0..63) x 48 quads, pad 49 (~50KB)
    __shared__ float sred[8 * 64];
    int tid = threadIdx.x;
    for (int idx = tid; idx < 64 * 48; idx += 256) {
        int j = idx >> 6;          // wrong split? 64*48 = 3072; use j = idx/48
        j = idx / 48;
        int q = idx - j * 48;
        float4 w;
        w.x = W_nb[(4 * q + 0) * NH + j];
        w.y = W_nb[(4 * q + 1) * NH + j];
        w.z = W_nb[(4 * q + 2) * NH + j];
        w.w = W_nb[(4 * q + 3) * NH + j];
        sW[j * 49 + q] = w;
    }
    __syncthreads();
    int lane = tid & 31, wid = tid >> 5;
    int gn0 = blockIdx.x * 64 + wid * 8;
    size_t off[8];
#pragma unroll
    for (int n = 0; n < 8; n++) {
        int gn = gn0 + n;
        off[n] = (size_t)((gn < N_C) ? gn : 0) * 64;
    }
    float aA[8], aB[8];
#pragma unroll
    for (int n = 0; n < 8; n++) { aA[n] = 0.f; aB[n] = 0.f; }
#pragma unroll
    for (int q = 0; q < 16; q++) {
        float4 wa = sW[lane * 49 + q], wb = sW[(lane + 32) * 49 + q];
#pragma unroll
        for (int n = 0; n < 8; n++) {
            float4 v = *(const float4*)&xin[off[n] + 4 * q];
            aA[n] += dot4(v, wa); aB[n] += dot4(v, wb);
        }
    }
#pragma unroll
    for (int q = 0; q < 16; q++) {
        float4 wa = sW[lane * 49 + 16 + q], wb = sW[(lane + 32) * 49 + 16 + q];
#pragma unroll
        for (int n = 0; n < 8; n++) {
            float4 v = *(const float4*)&hx[off[n] + 4 * q];
            aA[n] += dot4(v, wa); aB[n] += dot4(v, wb);
        }
    }
#pragma unroll
    for (int q = 0; q < 16; q++) {
        float4 wa = sW[lane * 49 + 32 + q], wb = sW[(lane + 32) * 49 + 32 + q];
#pragma unroll
        for (int n = 0; n < 8; n++) {
            float4 v = *(const float4*)&accbuf[off[n] + 4 * q];
            aA[n] += dot4(v, wa); aB[n] += dot4(v, wb);
        }
    }
    float gA = d_gcn[lane], gB = d_gcn[32 + lane];
    float sA = 0.f, sB = 0.f;
#pragma unroll
    for (int n = 0; n < 8; n++) {
        int gn = gn0 + n;
        if (gn < N_C) {
            float lo = fmaxf(aA[n] + gA, 0.f);
            float hi = fmaxf(aB[n] + gB, 0.f);
            xsout[(size_t)gn * 64 + lane] = lo;
            xsout[(size_t)gn * 64 + 32 + lane] = hi;
            if (tdout) {
                float h0 = hx[(size_t)gn * 64 + lane];
                float h1 = hx[(size_t)gn * 64 + 32 + lane];
                tdout[(size_t)gn * 64 + lane] = lo - h0;
                tdout[(size_t)gn * 64 + 32 + lane] = hi - h1;
            }
            sA += lo; sB += hi;
        }
    }
    sred[wid * 64 + lane] = sA;
    sred[wid * 64 + 32 + lane] = sB;
    __syncthreads();
    if (tid < 64) {
        float s2 = 0.f;
#pragma unroll
        for (int w = 0; w < 8; w++) s2 += sred[w * 64 + tid];
        atomicAdd(&d_xsum[tid], s2);
    }
}

// ---------------- sder / resid / decode ----------------
__global__ __launch_bounds__(256) void k_sder(const int* __restrict__ eidx,
                                              const float* __restrict__ spL,
                                              const float* __restrict__ coeff,
                                              const float* __restrict__ xs,
                                              float* __restrict__ sd) {
    int tid = threadIdx.x, lane = tid & 31, wid = tid >> 5;
    int e = blockIdx.x * 8 + wid;
    int s = eidx[e], r = eidx[E_C + e];
    float cw = coeff[0] * spL[e];
    size_t bs = (size_t)s * NH, br = (size_t)r * NH;
    float d0 = cw * (xs[bs + lane] - xs[br + lane]);
    float d1 = cw * (xs[bs + 32 + lane] - xs[br + 32 + lane]);
    atomicAdd(&sd[br + lane], d0);
    atomicAdd(&sd[br + 32 + lane], d1);
}

__global__ __launch_bounds__(256) void k_resid(float* __restrict__ a, const float* __restrict__ b) {
    int i = blockIdx.x * 256 + threadIdx.x;
    a[i] += b[i];
}

__global__ __launch_bounds__(256) void k_decode(const float* __restrict__ xa,
                                                const float* __restrict__ xb,
                                                const float* __restrict__ W1,
                                                const float* __restrict__ b1,
                                                const float* __restrict__ W2,
                                                const float* __restrict__ b2,
                                                float* __restrict__ outn) {
    __shared__ float4 sW[32 * 17];   // out j(0..31 lanes? no: W1 is 64x64) -> use 64x16 quads? keep simple
    __shared__ float sw2[NH];
    // W1: K=64, out=64. lane=out j for lo (j<32) and hi (j>=32).
    // Layout: row j (0..63), 16 quads, pad 17 -> 64*17 float4 = 17KB
    __shared__ float4 sW1[64 * 17];
    int tid = threadIdx.x;
    for (int idx = tid; idx < 64 * 16; idx += 256) {
        int j = idx >> 4, q = idx & 15;
        float4 w;
        w.x = W1[(4 * q + 0) * NH + j];
        w.y = W1[(4 * q + 1) * NH + j];
        w.z = W1[(4 * q + 2) * NH + j];
        w.w = W1[(4 * q + 3) * NH + j];
        sW1[j * 17 + q] = w;
    }
    if (tid < NH) sw2[tid] = W2[tid];
    __syncthreads();
    int lane = tid & 31, wid = tid >> 5;
    int row0 = blockIdx.x * 64 + wid * 8;
    size_t off[8];
#pragma unroll
    for (int n = 0; n < 8; n++) off[n] = (size_t)(row0 + n) * 64;
    float aA[8], aB[8];
#pragma unroll
    for (int n = 0; n < 8; n++) { aA[n] = 0.f; aB[n] = 0.f; }
#pragma unroll
    for (int q = 0; q < 16; q++) {
        float4 wa = sW1[lane * 17 + q], wb = sW1[(lane + 32) * 17 + q];
#pragma unroll
        for (int n = 0; n < 8; n++) {
            const float* pa = &xa[off[n] + 4 * q];
            const float* pb = &xb[off[n] + 4 * q];
            float4 va = *(const float4*)pa;
            float4 vb = *(const float4*)pb;
            float4 v;
            v.x = va.x + vb.x; v.y = va.y + vb.y; v.z = va.z + vb.z; v.w = va.w + vb.w;
            aA[n] += dot4(v, wa); aB[n] += dot4(v, wb);
        }
    }
    float b1a = b1[lane], b1b = b1[32 + lane];
    float w2a = sw2[lane], w2b = sw2[32 + lane];
#pragma unroll
    for (int n = 0; n < 8; n++) {
        float lo = fmaxf(aA[n] + b1a, 0.f);
        float hi = fmaxf(aB[n] + b1b, 0.f);
        float p = lo * w2a + hi * w2b;
#pragma unroll
        for (int o = 16; o; o >>= 1) p += __shfl_down_sync(0xffffffffu, p, o);
        if (lane == 0) outn[row0 + n] = p + b2[0];
    }
}

// ---------------- host launcher ----------------
extern "C" void kernel_launch(void* const* d_in, const int* in_sizes, int n_in,
                              void* d_out, int out_size) {
    const float* node_attr  = (const float*)d_in[0];
    const float* edge_attr  = (const float*)d_in[1];
    const int*   edge_index = (const int*)  d_in[2];
    const float* spL        = (const float*)d_in[3];
    const float* gattr      = (const float*)d_in[4];
    const float* coeff      = (const float*)d_in[5];
    const float* W_ee = (const float*)d_in[6];
    const float* b_ee = (const float*)d_in[7];
    const float* W_ne = (const float*)d_in[8];
    const float* b_ne = (const float*)d_in[9];
    const float* W_eb = (const float*)d_in[10];
    const float* b_eb = (const float*)d_in[11];
    const float* W_nb = (const float*)d_in[12];
    const float* b_nb = (const float*)d_in[13];
    const float* W_gb = (const float*)d_in[14];
    const float* b_gb = (const float*)d_in[15];
    const float* W_nd1 = (const float*)d_in[16];
    const float* b_nd1 = (const float*)d_in[17];
    const float* W_nd2 = (const float*)d_in[18];
    const float* b_nd2 = (const float*)d_in[19];

    float* out    = (float*)d_out;
    float* out_td = out + (size_t)T_C * N_C;
    float* out_sd = out_td + (size_t)T_C * N_C * NH;

    float *xenc, *xsA, *xsB, *es0, *e1, *hx0, *ns, *acc, *gsave, *esum, *xsum;
    cudaGetSymbolAddress((void**)&xenc, d_xenc);
    cudaGetSymbolAddress((void**)&xsA,  d_xsA);
    cudaGetSymbolAddress((void**)&xsB,  d_xsB);
    cudaGetSymbolAddress((void**)&es0,  d_es0);
    cudaGetSymbolAddress((void**)&e1,   d_e1);
    cudaGetSymbolAddress((void**)&hx0,  d_hx0);
    cudaGetSymbolAddress((void**)&ns,   d_ns);
    cudaGetSymbolAddress((void**)&acc,  d_acc);
    cudaGetSymbolAddress((void**)&gsave, d_gsave);
    cudaGetSymbolAddress((void**)&esum, d_esum);
    cudaGetSymbolAddress((void**)&xsum, d_xsum);

    const int NGRID = (N_C + 63) / 64;   // 313
    const int EGRID = E_C / 128;         // 2500

    cudaMemsetAsync(hx0, 0, (size_t)N_C * NH * sizeof(float));
    cudaMemsetAsync(esum, 0, EH * sizeof(float));
    cudaMemsetAsync(xsum, 0, NH * sizeof(float));
    cudaMemsetAsync(out_sd, 0, (size_t)T_C * N_C * NH * sizeof(float));

    k_encode<<<(T_C * N_C * NH) / 256, 256>>>(node_attr, W_ne, b_ne, xenc);
    k_prep<<<1, 32>>>(W_ee, b_ee, W_eb);

    // ---------------- layer 0 ----------------
    k_ginit<<<1, 96>>>(gattr, W_eb, b_eb, W_nb, b_nb);
    for (int t = 0; t < T_C; t++) {
        const float* xin = xenc + (size_t)t * N_C * NH;
        const float* hx = t ? (xsA + (size_t)(t - 1) * N_C * NH) : hx0;
        k_nodepre3<<<NGRID, 256>>>(xin, hx, W_eb, ns, acc);
        if (t == 0)
            k_edge3<true, false><<<EGRID, 256>>>(edge_index, edge_attr + (size_t)t * E_C,
                                                 nullptr, nullptr,
                                                 es0 + (size_t)t * E_C * EH, ns, acc,
                                                 W_eb, W_ee, b_ee);
        else
            k_edge3<true, true><<<EGRID, 256>>>(edge_index, edge_attr + (size_t)t * E_C,
                                                nullptr, es0 + (size_t)(t - 1) * E_C * EH,
                                                es0 + (size_t)t * E_C * EH, ns, acc,
                                                W_eb, W_ee, b_ee);
        k_node3<<<NGRID, 256>>>(xin, hx, acc, W_nb,
                                xsA + (size_t)t * N_C * NH, nullptr);
        if (t < T_C - 1)
            k_global<<<1, 256>>>(W_gb, b_gb, W_eb, b_eb, W_nb, b_nb, t == 0 ? 1 : 0);
    }

    k_resid<<<(T_C * N_C * NH) / 256, 256>>>(xsA, xenc);
    cudaMemsetAsync(esum, 0, EH * sizeof(float));
    cudaMemsetAsync(xsum, 0, NH * sizeof(float));

    // ---------------- layer 1 ----------------
    k_ginit<<<1, 96>>>(gsave, W_eb, b_eb, W_nb, b_nb);
    for (int t = 0; t < T_C; t++) {
        const float* xin = xsA + (size_t)t * N_C * NH;
        const float* hx = t ? (xsB + (size_t)(t - 1) * N_C * NH) : hx0;
        k_nodepre3<<<NGRID, 256>>>(xin, hx, W_eb, ns, acc);
        if (t == 0)
            k_edge3<false, false><<<EGRID, 256>>>(edge_index, nullptr,
                                                  es0 + (size_t)t * E_C * EH, nullptr,
                                                  e1, ns, acc, W_eb, W_ee, b_ee);
        else
            k_edge3<false, true><<<EGRID, 256>>>(edge_index, nullptr,
                                                 es0 + (size_t)t * E_C * EH, e1,
                                                 e1, ns, acc, W_eb, W_ee, b_ee);
        k_node3<<<NGRID, 256>>>(xin, hx, acc, W_nb,
                                xsB + (size_t)t * N_C * NH,
                                out_td + (size_t)t * N_C * NH);
        if (t < T_C - 1)
            k_global<<<1, 256>>>(W_gb, b_gb, W_eb, b_eb, W_nb, b_nb, 0);
        k_sder<<<E_C / 8, 256>>>(edge_index, spL, coeff,
                                 xsB + (size_t)t * N_C * NH,
                                 out_sd + (size_t)t * N_C * NH);
    }

    // decode over all T*N rows (T*N = 80000, 64 rows/block)
    k_decode<<<(T_C * N_C) / 64, 256>>>(xsA, xsB, W_nd1, b_nd1, W_nd2, b_nd2, out);
}